// round 1
// baseline (speedup 1.0000x reference)
#include <cuda_runtime.h>
#include <math.h>

#define N_NODE 100000
#define N_EDGE 625000
#define DD 128
#define AA 64
#define NRELROWS 401
#define NB 100

// ---- scratch (device globals; no runtime allocation allowed) ----
__device__ float g_sWs[(size_t)N_NODE * AA];   // hidden @ Ws        [N,64]
__device__ float g_rWr[NRELROWS * AA];         // rela_embed @ Wr    [401,64]
__device__ float g_qW[NB * AA];                // rela[q_rel]@Wqr+b  [100,64]
__device__ float g_agg[(size_t)N_NODE * DD];   // segment_sum target [N,128]
__device__ float g_hn[(size_t)N_NODE * DD];    // relu(agg @ W_h)    [N,128]
__device__ int   g_h0nz;                       // 1 if h0 has any nonzero

__device__ __forceinline__ float sigmoidf_(float x) {
    return 1.0f / (1.0f + expf(-x));
}

// ---------------------------------------------------------------------------
// zero agg + reset h0-nonzero flag
// ---------------------------------------------------------------------------
__global__ void zero_kernel() {
    const size_t total = (size_t)N_NODE * DD / 4;
    float4 z = make_float4(0.f, 0.f, 0.f, 0.f);
    float4* p = (float4*)g_agg;
    size_t stride = (size_t)gridDim.x * blockDim.x;
    for (size_t i = (size_t)blockIdx.x * blockDim.x + threadIdx.x; i < total; i += stride)
        p[i] = z;
    if (blockIdx.x == 0 && threadIdx.x == 0) g_h0nz = 0;
}

// ---------------------------------------------------------------------------
// h0 == 0 detector (lets us skip the h0 @ W_hh^T GEMM when h0 is all zeros)
// ---------------------------------------------------------------------------
__global__ void h0check_kernel(const float* __restrict__ h0) {
    const size_t total = (size_t)N_NODE * DD / 4;
    const float4* p = (const float4*)h0;
    size_t stride = (size_t)gridDim.x * blockDim.x;
    bool nz = false;
    for (size_t i = (size_t)blockIdx.x * blockDim.x + threadIdx.x; i < total; i += stride) {
        float4 v = p[i];
        if (v.x != 0.f || v.y != 0.f || v.z != 0.f || v.w != 0.f) { nz = true; break; }
    }
    if (nz) atomicOr(&g_h0nz, 1);
}

// ---------------------------------------------------------------------------
// tiny GEMMs: g_rWr = rela_embed @ Wr ; g_qW = rela_embed[q_rel] @ Wqr + b_qr
// one block (64 threads) per output row
// ---------------------------------------------------------------------------
__global__ void small_kernel(const float* __restrict__ re,
                             const float* __restrict__ Wr,
                             const float* __restrict__ Wqr,
                             const float* __restrict__ b_qr,
                             const int* __restrict__ q_rel) {
    int b = blockIdx.x;
    int c = threadIdx.x;  // 0..63
    const float* row;
    const float* W;
    float* out;
    float acc;
    if (b < NRELROWS) {
        row = re + (size_t)b * DD;
        W = Wr;
        out = g_rWr + b * AA;
        acc = 0.f;
    } else {
        int bb = b - NRELROWS;
        row = re + (size_t)__ldg(&q_rel[bb]) * DD;
        W = Wqr;
        out = g_qW + bb * AA;
        acc = __ldg(&b_qr[c]);
    }
    for (int k = 0; k < DD; k++)
        acc += __ldg(&row[k]) * __ldg(&W[k * AA + c]);
    out[c] = acc;
}

// ---------------------------------------------------------------------------
// g_sWs = hidden @ Ws   (N x 128 @ 128 x 64)
// block: 256 threads, 64 rows; Ws + hidden tile in smem
// ---------------------------------------------------------------------------
#define SWS_SMEM (DD * AA * 4 + 64 * 132 * 4)  // 32768 + 33792 = 66560
__global__ void sws_kernel(const float* __restrict__ hidden,
                           const float* __restrict__ Ws) {
    extern __shared__ float sm[];
    float* sW = sm;                 // [128][64]
    float* sH = sm + DD * AA;       // [64][132]
    int tid = threadIdx.x;
    int rowBase = blockIdx.x * 64;

    float4* sW4 = (float4*)sW;
    const float4* Wv = (const float4*)Ws;
    for (int i = tid; i < DD * AA / 4; i += 256) sW4[i] = Wv[i];

    const float4* hv = (const float4*)hidden;
    for (int i = tid; i < 64 * 32; i += 256) {
        int r = i >> 5, kv = i & 31;
        int gr = rowBase + r;
        float4 v = (gr < N_NODE) ? hv[(size_t)gr * 32 + kv] : make_float4(0, 0, 0, 0);
        *(float4*)&sH[r * 132 + kv * 4] = v;
    }
    __syncthreads();

    int r = tid >> 2;   // 0..63
    int cg = tid & 3;   // float4 lane within 16-float4 row
    float4 acc[4];
#pragma unroll
    for (int j = 0; j < 4; j++) acc[j] = make_float4(0, 0, 0, 0);

    for (int k = 0; k < DD; k++) {
        float h = sH[r * 132 + k];
        const float4* wr = (const float4*)&sW[k * AA];
#pragma unroll
        for (int j = 0; j < 4; j++) {
            float4 w = wr[cg + 4 * j];
            acc[j].x += h * w.x; acc[j].y += h * w.y;
            acc[j].z += h * w.z; acc[j].w += h * w.w;
        }
    }
    int gr = rowBase + r;
    if (gr < N_NODE) {
        float4* o = (float4*)(g_sWs + (size_t)gr * AA);
#pragma unroll
        for (int j = 0; j < 4; j++) o[cg + 4 * j] = acc[j];
    }
}

// ---------------------------------------------------------------------------
// edge kernel: one warp per edge
//   attn = relu(sWs[sub] + rWr[rel] + qW[r_idx]);  alpha = sigmoid(attn.w_alpha + b)
//   red.global.add.v4 alpha*(hidden[sub] + rela[rel]) into g_agg[obj]
// ---------------------------------------------------------------------------
__global__ void edge_kernel(const float* __restrict__ hidden,
                            const float* __restrict__ rela,
                            const float* __restrict__ w_alpha,
                            const float* __restrict__ b_alpha,
                            const int* __restrict__ r_idx,
                            const int* __restrict__ rel,
                            const int* __restrict__ sub,
                            const int* __restrict__ obj) {
    int e = (blockIdx.x * blockDim.x + threadIdx.x) >> 5;
    int lane = threadIdx.x & 31;
    if (e >= N_EDGE) return;

    int s  = __ldg(&sub[e]);
    int rl = __ldg(&rel[e]);
    int ri = __ldg(&r_idx[e]);
    int o  = __ldg(&obj[e]);

    const float2* sWs2 = (const float2*)g_sWs;
    const float2* rWr2 = (const float2*)g_rWr;
    const float2* qW2  = (const float2*)g_qW;

    float2 a0 = sWs2[(size_t)s * 32 + lane];
    float2 a1 = rWr2[rl * 32 + lane];
    float2 a2 = qW2[ri * 32 + lane];
    float ax = fmaxf(a0.x + a1.x + a2.x, 0.f);
    float ay = fmaxf(a0.y + a1.y + a2.y, 0.f);

    float2 wa = ((const float2*)w_alpha)[lane];
    float d = ax * wa.x + ay * wa.y;
#pragma unroll
    for (int off = 16; off; off >>= 1)
        d += __shfl_xor_sync(0xffffffffu, d, off);

    float alpha = sigmoidf_(d + __ldg(&b_alpha[0]));

    const float4* hv = (const float4*)hidden;
    const float4* rv = (const float4*)rela;
    float4 h4 = hv[(size_t)s * 32 + lane];
    float4 r4 = rv[(size_t)rl * 32 + lane];
    float4 m;
    m.x = alpha * (h4.x + r4.x);
    m.y = alpha * (h4.y + r4.y);
    m.z = alpha * (h4.z + r4.z);
    m.w = alpha * (h4.w + r4.w);

    float* dst = &g_agg[(size_t)o * DD + lane * 4];
    asm volatile("red.global.add.v4.f32 [%0], {%1,%2,%3,%4};"
                 :: "l"(dst), "f"(m.x), "f"(m.y), "f"(m.z), "f"(m.w)
                 : "memory");
}

// ---------------------------------------------------------------------------
// g_hn = relu(g_agg @ W_h)   (N x 128 @ 128 x 128)
// block: 256 threads, 64 rows
// ---------------------------------------------------------------------------
#define D1_SMEM (DD * DD * 4 + 64 * 132 * 4)  // 65536 + 33792 = 99328
__global__ void d1_kernel(const float* __restrict__ W_h) {
    extern __shared__ float sm[];
    float* sW = sm;                  // [128][128]
    float* sH = sm + DD * DD;        // [64][132]
    int tid = threadIdx.x;
    int rowBase = blockIdx.x * 64;

    float4* sW4 = (float4*)sW;
    const float4* Wv = (const float4*)W_h;
    for (int i = tid; i < DD * DD / 4; i += 256) sW4[i] = Wv[i];

    const float4* av = (const float4*)g_agg;
    for (int i = tid; i < 64 * 32; i += 256) {
        int r = i >> 5, kv = i & 31;
        int gr = rowBase + r;
        float4 v = (gr < N_NODE) ? av[(size_t)gr * 32 + kv] : make_float4(0, 0, 0, 0);
        *(float4*)&sH[r * 132 + kv * 4] = v;
    }
    __syncthreads();

    int r = tid >> 2;   // 0..63
    int cg = tid & 3;
    float4 acc[8];
#pragma unroll
    for (int j = 0; j < 8; j++) acc[j] = make_float4(0, 0, 0, 0);

    for (int k = 0; k < DD; k++) {
        float h = sH[r * 132 + k];
        const float4* wr = (const float4*)&sW[k * DD];
#pragma unroll
        for (int j = 0; j < 8; j++) {
            float4 w = wr[cg + 4 * j];
            acc[j].x += h * w.x; acc[j].y += h * w.y;
            acc[j].z += h * w.z; acc[j].w += h * w.w;
        }
    }
    int gr = rowBase + r;
    if (gr < N_NODE) {
        float4* o = (float4*)(g_hn + (size_t)gr * DD);
#pragma unroll
        for (int j = 0; j < 8; j++) {
            float4 v = acc[j];
            v.x = fmaxf(v.x, 0.f); v.y = fmaxf(v.y, 0.f);
            v.z = fmaxf(v.z, 0.f); v.w = fmaxf(v.w, 0.f);
            o[cg + 4 * j] = v;
        }
    }
}

// ---------------------------------------------------------------------------
// GRU: gi = hn @ W_ih^T + b_ih ; gh = h0 @ W_hh^T + b_hh (skipped if h0==0)
// gates -> h_out.   block: 256 threads, 32 rows; W_ih fully in smem [384][132]
// ---------------------------------------------------------------------------
#define D2_SMEM (3 * DD * 132 * 4 + 32 * 132 * 4)  // 202752 + 16896 = 219648
__global__ void d2_kernel(const float* __restrict__ W_ih,
                          const float* __restrict__ W_hh,
                          const float* __restrict__ b_ih,
                          const float* __restrict__ b_hh,
                          const float* __restrict__ h0,
                          float* __restrict__ out) {
    extern __shared__ float sm[];
    float4* sW4 = (float4*)sm;                       // [384][33] float4 (132 floats/row)
    float4* sH4 = (float4*)(sm + 3 * DD * 132);      // [32][33]  float4
    int tid = threadIdx.x;
    int rowBase = blockIdx.x * 32;

    const float4* Wv = (const float4*)W_ih;
    for (int f = tid; f < 3 * DD * 32; f += 256) {
        int j = f >> 5, kv = f & 31;
        sW4[j * 33 + kv] = Wv[f];
    }
    const float4* hnv = (const float4*)g_hn;
    for (int f = tid; f < 32 * 32; f += 256) {
        int r = f >> 5, kv = f & 31;
        int gr = rowBase + r;
        sH4[r * 33 + kv] = (gr < N_NODE) ? hnv[(size_t)gr * 32 + kv]
                                         : make_float4(0, 0, 0, 0);
    }
    __syncthreads();

    int r = tid >> 3;   // 0..31
    int cg = tid & 7;   // column class: c = cg + 8*i
    int row = rowBase + r;

    float accR[16], accZ[16], accN[16];
#pragma unroll
    for (int i = 0; i < 16; i++) { accR[i] = 0.f; accZ[i] = 0.f; accN[i] = 0.f; }

    for (int kv = 0; kv < 32; kv++) {
        float4 h = sH4[r * 33 + kv];
#pragma unroll
        for (int i = 0; i < 16; i++) {
            int j0 = cg + 8 * i;
            float4 w = sW4[j0 * 33 + kv];
            accR[i] += h.x * w.x + h.y * w.y + h.z * w.z + h.w * w.w;
            w = sW4[(128 + j0) * 33 + kv];
            accZ[i] += h.x * w.x + h.y * w.y + h.z * w.z + h.w * w.w;
            w = sW4[(256 + j0) * 33 + kv];
            accN[i] += h.x * w.x + h.y * w.y + h.z * w.z + h.w * w.w;
        }
    }

    int flag = g_h0nz;
    float ghN[16];
#pragma unroll
    for (int i = 0; i < 16; i++) ghN[i] = __ldg(&b_hh[256 + cg + 8 * i]);

    if (flag) {  // general path: gh = h0 @ W_hh^T (cold in this dataset)
        __syncthreads();
        const float4* Wv2 = (const float4*)W_hh;
        for (int f = tid; f < 3 * DD * 32; f += 256) {
            int j = f >> 5, kv = f & 31;
            sW4[j * 33 + kv] = Wv2[f];
        }
        __syncthreads();
        const float4* h0v = (const float4*)h0;
        for (int kv = 0; kv < 32; kv++) {
            float4 h = (row < N_NODE) ? __ldg(&h0v[(size_t)row * 32 + kv])
                                      : make_float4(0, 0, 0, 0);
#pragma unroll
            for (int i = 0; i < 16; i++) {
                int j0 = cg + 8 * i;
                float4 w = sW4[j0 * 33 + kv];
                accR[i] += h.x * w.x + h.y * w.y + h.z * w.z + h.w * w.w;
                w = sW4[(128 + j0) * 33 + kv];
                accZ[i] += h.x * w.x + h.y * w.y + h.z * w.z + h.w * w.w;
                w = sW4[(256 + j0) * 33 + kv];
                ghN[i] += h.x * w.x + h.y * w.y + h.z * w.z + h.w * w.w;
            }
        }
    }

    if (row < N_NODE) {
#pragma unroll
        for (int i = 0; i < 16; i++) {
            int c = cg + 8 * i;
            float rr = sigmoidf_(accR[i] + __ldg(&b_ih[c]) + __ldg(&b_hh[c]));
            float zz = sigmoidf_(accZ[i] + __ldg(&b_ih[128 + c]) + __ldg(&b_hh[128 + c]));
            float nn = tanhf(accN[i] + __ldg(&b_ih[256 + c]) + rr * ghN[i]);
            float h0v = flag ? __ldg(&h0[(size_t)row * DD + c]) : 0.f;
            out[(size_t)row * DD + c] = (1.f - zz) * nn + zz * h0v;
        }
    }
}

// ---------------------------------------------------------------------------
extern "C" void kernel_launch(void* const* d_in, const int* in_sizes, int n_in,
                              void* d_out, int out_size) {
    const float* hidden  = (const float*)d_in[0];
    const float* rela    = (const float*)d_in[1];
    const float* Ws      = (const float*)d_in[2];
    const float* Wr      = (const float*)d_in[3];
    const float* Wqr     = (const float*)d_in[4];
    const float* b_qr    = (const float*)d_in[5];
    const float* w_alpha = (const float*)d_in[6];
    const float* b_alpha = (const float*)d_in[7];
    const float* W_h     = (const float*)d_in[8];
    const float* W_ih    = (const float*)d_in[9];
    const float* W_hh    = (const float*)d_in[10];
    const float* b_ih    = (const float*)d_in[11];
    const float* b_hh    = (const float*)d_in[12];
    const float* h0      = (const float*)d_in[13];
    const int* q_rel     = (const int*)d_in[14];
    const int* r_idx     = (const int*)d_in[15];
    const int* rel       = (const int*)d_in[16];
    const int* sub       = (const int*)d_in[17];
    const int* obj       = (const int*)d_in[18];
    float* out = (float*)d_out;

    cudaFuncSetAttribute(sws_kernel, cudaFuncAttributeMaxDynamicSharedMemorySize, SWS_SMEM);
    cudaFuncSetAttribute(d1_kernel, cudaFuncAttributeMaxDynamicSharedMemorySize, D1_SMEM);
    cudaFuncSetAttribute(d2_kernel, cudaFuncAttributeMaxDynamicSharedMemorySize, D2_SMEM);

    zero_kernel<<<512, 256>>>();
    h0check_kernel<<<512, 256>>>(h0);
    small_kernel<<<NRELROWS + NB, 64>>>(rela, Wr, Wqr, b_qr, q_rel);
    sws_kernel<<<(N_NODE + 63) / 64, 256, SWS_SMEM>>>(hidden, Ws);
    edge_kernel<<<(N_EDGE * 32 + 255) / 256, 256>>>(hidden, rela, w_alpha, b_alpha,
                                                    r_idx, rel, sub, obj);
    d1_kernel<<<(N_NODE + 63) / 64, 256, D1_SMEM>>>(W_h);
    d2_kernel<<<(N_NODE + 31) / 32, 256, D2_SMEM>>>(W_ih, W_hh, b_ih, b_hh, h0, out);
}

// round 4
// speedup vs baseline: 2.4871x; 2.4871x over previous
#include <cuda_runtime.h>
#include <math.h>
#include <stdint.h>

#define N_NODE 100000
#define N_EDGE 625000
#define DD 128
#define AA 64
#define NRELROWS 401
#define NB 100

// ---- scratch (device globals; no runtime allocation allowed) ----
__device__ float g_sWs[(size_t)N_NODE * AA];   // hidden @ Ws        [N,64]
__device__ float g_rWr[NRELROWS * AA];         // rela_embed @ Wr    [401,64]
__device__ float g_qW[NB * AA];                // rela[q_rel]@Wqr+b  [100,64]
__device__ float g_agg[(size_t)N_NODE * DD];   // segment_sum target [N,128]
__device__ float g_hn[(size_t)N_NODE * DD];    // relu(agg @ W_h)    [N,128]
__device__ int   g_h0nz;                       // 1 if h0 has any nonzero

__device__ __forceinline__ float sigmoidf_(float x) {
    return 1.0f / (1.0f + expf(-x));
}

__device__ __forceinline__ uint32_t f2tf32(float v) {
    uint32_t r;
    asm("cvt.rna.tf32.f32 %0, %1;" : "=r"(r) : "f"(v));
    return r;
}

__device__ __forceinline__ void mma_tf32(float4& c, const uint32_t a[4], const uint32_t b[2]) {
    asm volatile(
        "mma.sync.aligned.m16n8k8.row.col.f32.tf32.tf32.f32 "
        "{%0,%1,%2,%3}, {%4,%5,%6,%7}, {%8,%9}, {%0,%1,%2,%3};"
        : "+f"(c.x), "+f"(c.y), "+f"(c.z), "+f"(c.w)
        : "r"(a[0]), "r"(a[1]), "r"(a[2]), "r"(a[3]), "r"(b[0]), "r"(b[1]));
}

// ---------------------------------------------------------------------------
// zero agg + reset h0-nonzero flag
// ---------------------------------------------------------------------------
__global__ void zero_kernel() {
    const size_t total = (size_t)N_NODE * DD / 4;
    float4 z = make_float4(0.f, 0.f, 0.f, 0.f);
    float4* p = (float4*)g_agg;
    size_t stride = (size_t)gridDim.x * blockDim.x;
    for (size_t i = (size_t)blockIdx.x * blockDim.x + threadIdx.x; i < total; i += stride)
        p[i] = z;
    if (blockIdx.x == 0 && threadIdx.x == 0) g_h0nz = 0;
}

// ---------------------------------------------------------------------------
// h0 == 0 detector
// ---------------------------------------------------------------------------
__global__ void h0check_kernel(const float* __restrict__ h0) {
    const size_t total = (size_t)N_NODE * DD / 4;
    const float4* p = (const float4*)h0;
    size_t stride = (size_t)gridDim.x * blockDim.x;
    bool nz = false;
    for (size_t i = (size_t)blockIdx.x * blockDim.x + threadIdx.x; i < total; i += stride) {
        float4 v = p[i];
        if (v.x != 0.f || v.y != 0.f || v.z != 0.f || v.w != 0.f) { nz = true; break; }
    }
    if (nz) atomicOr(&g_h0nz, 1);
}

// ---------------------------------------------------------------------------
// tiny GEMMs: g_rWr = rela_embed @ Wr ; g_qW = rela_embed[q_rel] @ Wqr + b_qr
// ---------------------------------------------------------------------------
__global__ void small_kernel(const float* __restrict__ re,
                             const float* __restrict__ Wr,
                             const float* __restrict__ Wqr,
                             const float* __restrict__ b_qr,
                             const int* __restrict__ q_rel) {
    int b = blockIdx.x;
    int c = threadIdx.x;  // 0..63
    const float* row;
    const float* W;
    float* out;
    float acc;
    if (b < NRELROWS) {
        row = re + (size_t)b * DD;
        W = Wr;
        out = g_rWr + b * AA;
        acc = 0.f;
    } else {
        int bb = b - NRELROWS;
        row = re + (size_t)__ldg(&q_rel[bb]) * DD;
        W = Wqr;
        out = g_qW + bb * AA;
        acc = __ldg(&b_qr[c]);
    }
    for (int k = 0; k < DD; k++)
        acc += __ldg(&row[k]) * __ldg(&W[k * AA + c]);
    out[c] = acc;
}

// ---------------------------------------------------------------------------
// TF32 tensor-core GEMM, K-major B (B is [K=128][NOUT] row-major):
//   C[M,NOUT] = op(A[M,128] @ B),  op = optional ReLU
// block 256 thr (8 warps 4m x 2n), M tile 128, full K resident in smem.
// used for: sws (NOUT=64, B=Ws), d1 (NOUT=128, B=W_h, relu)
// ---------------------------------------------------------------------------
template <int NOUT, bool RELU>
__global__ __launch_bounds__(256) void gemmk_kernel(const float* __restrict__ A,
                                                    const float* __restrict__ B,
                                                    float* __restrict__ C, int M) {
    constexpr int LDA = 132;
    constexpr int LDB = (NOUT == 128) ? 136 : 72;
    extern __shared__ uint32_t sm[];
    uint32_t* sA = sm;              // [128][LDA] tf32 bits
    uint32_t* sB = sm + 128 * LDA;  // [128][LDB]
    int tid = threadIdx.x;
    int rowBase = blockIdx.x * 128;

    const float4* Av = (const float4*)A;
    for (int i = tid; i < 128 * 32; i += 256) {
        int r = i >> 5, kv = i & 31;
        int gr = rowBase + r;
        float4 v = (gr < M) ? Av[(size_t)gr * 32 + kv] : make_float4(0, 0, 0, 0);
        uint32_t* d = &sA[r * LDA + kv * 4];
        d[0] = f2tf32(v.x); d[1] = f2tf32(v.y); d[2] = f2tf32(v.z); d[3] = f2tf32(v.w);
    }
    const float4* Bv = (const float4*)B;
    for (int i = tid; i < 128 * NOUT / 4; i += 256) {
        int r = i / (NOUT / 4), c4 = i % (NOUT / 4);
        float4 v = Bv[i];
        uint32_t* d = &sB[r * LDB + c4 * 4];
        d[0] = f2tf32(v.x); d[1] = f2tf32(v.y); d[2] = f2tf32(v.z); d[3] = f2tf32(v.w);
    }
    __syncthreads();

    int lane = tid & 31, wid = tid >> 5;
    int gp = lane >> 2, tg = lane & 3;
    int warp_m = wid & 3, warp_n = wid >> 2;
    constexpr int NF = NOUT / 16;  // n-frags per warp
    int m0 = warp_m * 32;
    int n0 = warp_n * (NOUT / 2);

    float4 acc[2][NF];
#pragma unroll
    for (int mf = 0; mf < 2; mf++)
#pragma unroll
        for (int nf = 0; nf < NF; nf++) acc[mf][nf] = make_float4(0, 0, 0, 0);

    for (int kb = 0; kb < 128; kb += 8) {
        uint32_t a[2][4];
#pragma unroll
        for (int mf = 0; mf < 2; mf++) {
            const uint32_t* ap = &sA[(m0 + mf * 16 + gp) * LDA + kb + tg];
            a[mf][0] = ap[0];
            a[mf][2] = ap[4];
            const uint32_t* ap2 = ap + 8 * LDA;
            a[mf][1] = ap2[0];
            a[mf][3] = ap2[4];
        }
#pragma unroll
        for (int nf = 0; nf < NF; nf++) {
            const uint32_t* bp = &sB[(kb + tg) * LDB + n0 + nf * 8 + gp];
            uint32_t b[2] = {bp[0], bp[4 * LDB]};
            mma_tf32(acc[0][nf], a[0], b);
            mma_tf32(acc[1][nf], a[1], b);
        }
    }

#pragma unroll
    for (int mf = 0; mf < 2; mf++) {
        int r0 = rowBase + m0 + mf * 16 + gp;
#pragma unroll
        for (int nf = 0; nf < NF; nf++) {
            int c = n0 + nf * 8 + 2 * tg;
            float4 v = acc[mf][nf];
            if (RELU) {
                v.x = fmaxf(v.x, 0.f); v.y = fmaxf(v.y, 0.f);
                v.z = fmaxf(v.z, 0.f); v.w = fmaxf(v.w, 0.f);
            }
            if (r0 < M)
                *(float2*)&C[(size_t)r0 * NOUT + c] = make_float2(v.x, v.y);
            if (r0 + 8 < M)
                *(float2*)&C[(size_t)(r0 + 8) * NOUT + c] = make_float2(v.z, v.w);
        }
    }
}

// ---------------------------------------------------------------------------
// edge kernel: one warp per edge
// ---------------------------------------------------------------------------
__global__ void edge_kernel(const float* __restrict__ hidden,
                            const float* __restrict__ rela,
                            const float* __restrict__ w_alpha,
                            const float* __restrict__ b_alpha,
                            const int* __restrict__ r_idx,
                            const int* __restrict__ rel,
                            const int* __restrict__ sub,
                            const int* __restrict__ obj) {
    int e = (blockIdx.x * blockDim.x + threadIdx.x) >> 5;
    int lane = threadIdx.x & 31;
    if (e >= N_EDGE) return;

    int s  = __ldg(&sub[e]);
    int rl = __ldg(&rel[e]);
    int ri = __ldg(&r_idx[e]);
    int o  = __ldg(&obj[e]);

    const float2* sWs2 = (const float2*)g_sWs;
    const float2* rWr2 = (const float2*)g_rWr;
    const float2* qW2  = (const float2*)g_qW;

    float2 a0 = sWs2[(size_t)s * 32 + lane];
    float2 a1 = rWr2[rl * 32 + lane];
    float2 a2 = qW2[ri * 32 + lane];
    float ax = fmaxf(a0.x + a1.x + a2.x, 0.f);
    float ay = fmaxf(a0.y + a1.y + a2.y, 0.f);

    float2 wa = ((const float2*)w_alpha)[lane];
    float d = ax * wa.x + ay * wa.y;
#pragma unroll
    for (int off = 16; off; off >>= 1)
        d += __shfl_xor_sync(0xffffffffu, d, off);

    float alpha = sigmoidf_(d + __ldg(&b_alpha[0]));

    const float4* hv = (const float4*)hidden;
    const float4* rv = (const float4*)rela;
    float4 h4 = hv[(size_t)s * 32 + lane];
    float4 r4 = rv[(size_t)rl * 32 + lane];
    float4 m;
    m.x = alpha * (h4.x + r4.x);
    m.y = alpha * (h4.y + r4.y);
    m.z = alpha * (h4.z + r4.z);
    m.w = alpha * (h4.w + r4.w);

    float* dst = &g_agg[(size_t)o * DD + lane * 4];
    asm volatile("red.global.add.v4.f32 [%0], {%1,%2,%3,%4};"
                 :: "l"(dst), "f"(m.x), "f"(m.y), "f"(m.z), "f"(m.w)
                 : "memory");
}

// ---------------------------------------------------------------------------
// GRU kernel: TF32 GEMM gi = g_hn @ W_ih^T (one 64-col gate chunk per block,
// all 3 gate sections resident) with gate math fused into the epilogue.
// grid (ceil(N/128), 2); block 256.  gh = b_hh when h0==0 (the common path);
// a correct (slow) fallback handles nonzero h0.
// ---------------------------------------------------------------------------
#define GRU_SMEM ((128 * 132 + 192 * 132) * 4)  // 168960
__global__ __launch_bounds__(256) void gru_kernel(const float* __restrict__ W_ih,
                                                  const float* __restrict__ W_hh,
                                                  const float* __restrict__ b_ih,
                                                  const float* __restrict__ b_hh,
                                                  const float* __restrict__ h0,
                                                  float* __restrict__ out) {
    constexpr int LDA = 132, LDB = 132;
    extern __shared__ uint32_t sm[];
    uint32_t* sA = sm;              // [128][132] hn rows, tf32
    uint32_t* sB = sm + 128 * LDA;  // [192][132] W_ih rows for 3 gate sections
    int tid = threadIdx.x;
    int rowBase = blockIdx.x * 128;
    int chunk = blockIdx.y;  // gate cols [chunk*64, chunk*64+64)

    const float4* Av = (const float4*)g_hn;
    for (int i = tid; i < 128 * 32; i += 256) {
        int r = i >> 5, kv = i & 31;
        int gr = rowBase + r;
        float4 v = (gr < N_NODE) ? Av[(size_t)gr * 32 + kv] : make_float4(0, 0, 0, 0);
        uint32_t* d = &sA[r * LDA + kv * 4];
        d[0] = f2tf32(v.x); d[1] = f2tf32(v.y); d[2] = f2tf32(v.z); d[3] = f2tf32(v.w);
    }
    const float4* Bv = (const float4*)W_ih;
    for (int i = tid; i < 192 * 32; i += 256) {
        int r = i >> 5, kv = i & 31;
        int g = r >> 6, j = r & 63;
        int grow = g * 128 + chunk * 64 + j;
        float4 v = Bv[(size_t)grow * 32 + kv];
        uint32_t* d = &sB[r * LDB + kv * 4];
        d[0] = f2tf32(v.x); d[1] = f2tf32(v.y); d[2] = f2tf32(v.z); d[3] = f2tf32(v.w);
    }
    __syncthreads();

    int lane = tid & 31, wid = tid >> 5;
    int gp = lane >> 2, tg = lane & 3;
    int warp_m = wid & 3, warp_n = wid >> 2;
    int m0 = warp_m * 32;

    float4 acc[2][12];
#pragma unroll
    for (int mf = 0; mf < 2; mf++)
#pragma unroll
        for (int nf = 0; nf < 12; nf++) acc[mf][nf] = make_float4(0, 0, 0, 0);

    for (int kb = 0; kb < 128; kb += 8) {
        uint32_t a[2][4];
#pragma unroll
        for (int mf = 0; mf < 2; mf++) {
            const uint32_t* ap = &sA[(m0 + mf * 16 + gp) * LDA + kb + tg];
            a[mf][0] = ap[0];
            a[mf][2] = ap[4];
            const uint32_t* ap2 = ap + 8 * LDA;
            a[mf][1] = ap2[0];
            a[mf][3] = ap2[4];
        }
#pragma unroll
        for (int nf = 0; nf < 12; nf++) {
            int g = nf >> 2, f = nf & 3;
            int brow = g * 64 + warp_n * 32 + f * 8 + gp;
            const uint32_t* bp = &sB[brow * LDB + kb + tg];
            uint32_t b[2] = {bp[0], bp[4]};
            mma_tf32(acc[0][nf], a[0], b);
            mma_tf32(acc[1][nf], a[1], b);
        }
    }

    int flag = g_h0nz;
#pragma unroll
    for (int mf = 0; mf < 2; mf++) {
        int r0 = rowBase + m0 + mf * 16 + gp;
#pragma unroll
        for (int f = 0; f < 4; f++) {
            float4 aR = acc[mf][f];
            float4 aZ = acc[mf][4 + f];
            float4 aN = acc[mf][8 + f];
            int cbase = chunk * 64 + warp_n * 32 + f * 8 + 2 * tg;
#pragma unroll
            for (int hi = 0; hi < 2; hi++) {
                int row = r0 + hi * 8;
                if (row >= N_NODE) continue;
                float vr[2] = {hi ? aR.z : aR.x, hi ? aR.w : aR.y};
                float vz[2] = {hi ? aZ.z : aZ.x, hi ? aZ.w : aZ.y};
                float vn[2] = {hi ? aN.z : aN.x, hi ? aN.w : aN.y};
                float o[2];
#pragma unroll
                for (int p = 0; p < 2; p++) {
                    int c = cbase + p;
                    float gr_ = vr[p] + __ldg(&b_ih[c]) + __ldg(&b_hh[c]);
                    float gz_ = vz[p] + __ldg(&b_ih[128 + c]) + __ldg(&b_hh[128 + c]);
                    float gn_ = vn[p] + __ldg(&b_ih[256 + c]);
                    float ghn = __ldg(&b_hh[256 + c]);
                    float h0v = 0.f;
                    if (flag) {  // cold general path: gh = h0 @ W_hh^T
                        float sR = 0.f, sZ = 0.f, sN = 0.f;
                        for (int k = 0; k < DD; k++) {
                            float hv = __ldg(&h0[(size_t)row * DD + k]);
                            sR += hv * __ldg(&W_hh[(size_t)c * DD + k]);
                            sZ += hv * __ldg(&W_hh[(size_t)(128 + c) * DD + k]);
                            sN += hv * __ldg(&W_hh[(size_t)(256 + c) * DD + k]);
                        }
                        gr_ += sR;
                        gz_ += sZ;
                        ghn += sN;
                        h0v = __ldg(&h0[(size_t)row * DD + c]);
                    }
                    float rr = sigmoidf_(gr_);
                    float zz = sigmoidf_(gz_);
                    float nn = tanhf(gn_ + rr * ghn);
                    o[p] = (1.f - zz) * nn + zz * h0v;
                }
                *(float2*)&out[(size_t)row * DD + cbase] = make_float2(o[0], o[1]);
            }
        }
    }
}

// ---------------------------------------------------------------------------
extern "C" void kernel_launch(void* const* d_in, const int* in_sizes, int n_in,
                              void* d_out, int out_size) {
    const float* hidden  = (const float*)d_in[0];
    const float* rela    = (const float*)d_in[1];
    const float* Ws      = (const float*)d_in[2];
    const float* Wr      = (const float*)d_in[3];
    const float* Wqr     = (const float*)d_in[4];
    const float* b_qr    = (const float*)d_in[5];
    const float* w_alpha = (const float*)d_in[6];
    const float* b_alpha = (const float*)d_in[7];
    const float* W_h     = (const float*)d_in[8];
    const float* W_ih    = (const float*)d_in[9];
    const float* W_hh    = (const float*)d_in[10];
    const float* b_ih    = (const float*)d_in[11];
    const float* b_hh    = (const float*)d_in[12];
    const float* h0      = (const float*)d_in[13];
    const int* q_rel     = (const int*)d_in[14];
    const int* r_idx     = (const int*)d_in[15];
    const int* rel       = (const int*)d_in[16];
    const int* sub       = (const int*)d_in[17];
    const int* obj       = (const int*)d_in[18];
    float* out = (float*)d_out;

    void *p_sWs, *p_agg, *p_hn;
    cudaGetSymbolAddress(&p_sWs, g_sWs);
    cudaGetSymbolAddress(&p_agg, g_agg);
    cudaGetSymbolAddress(&p_hn, g_hn);

    const int SWS_SMEM = (128 * 132 + 128 * 72) * 4;    // 104448
    const int D1_SMEM  = (128 * 132 + 128 * 136) * 4;   // 137216
    cudaFuncSetAttribute(gemmk_kernel<64, false>, cudaFuncAttributeMaxDynamicSharedMemorySize, SWS_SMEM);
    cudaFuncSetAttribute(gemmk_kernel<128, true>, cudaFuncAttributeMaxDynamicSharedMemorySize, D1_SMEM);
    cudaFuncSetAttribute(gru_kernel, cudaFuncAttributeMaxDynamicSharedMemorySize, GRU_SMEM);

    int nblk = (N_NODE + 127) / 128;  // 782

    zero_kernel<<<512, 256>>>();
    h0check_kernel<<<512, 256>>>(h0);
    small_kernel<<<NRELROWS + NB, 64>>>(rela, Wr, Wqr, b_qr, q_rel);
    gemmk_kernel<64, false><<<nblk, 256, SWS_SMEM>>>(hidden, Ws, (float*)p_sWs, N_NODE);
    edge_kernel<<<(N_EDGE * 32 + 255) / 256, 256>>>(hidden, rela, w_alpha, b_alpha,
                                                    r_idx, rel, sub, obj);
    gemmk_kernel<128, true><<<nblk, 256, D1_SMEM>>>((const float*)p_agg, W_h, (float*)p_hn, N_NODE);
    gru_kernel<<<dim3(nblk, 2), 256, GRU_SMEM>>>(W_ih, W_hh, b_ih, b_hh, h0, out);
}

// round 5
// speedup vs baseline: 2.8747x; 1.1558x over previous
#include <cuda_runtime.h>
#include <math.h>
#include <stdint.h>

#define N_NODE 100000
#define N_EDGE 625000
#define DD 128
#define AA 64
#define NRELROWS 401
#define NB 100

// ---- scratch (device globals; no runtime allocation allowed) ----
__device__ float g_sWs[(size_t)N_NODE * AA];   // hidden @ Ws        [N,64]
__device__ float g_rWr[NRELROWS * AA];         // rela_embed @ Wr    [401,64]
__device__ float g_qW[NB * AA];                // rela[q_rel]@Wqr+b  [100,64]
__device__ float g_agg[(size_t)N_NODE * DD];   // segment_sum target [N,128]
__device__ int   g_h0nz;                       // 1 if h0 has any nonzero

__device__ __forceinline__ float sigmoidf_(float x) {
    return 1.0f / (1.0f + expf(-x));
}

__device__ __forceinline__ uint32_t f2tf32(float v) {
    uint32_t r;
    asm("cvt.rna.tf32.f32 %0, %1;" : "=r"(r) : "f"(v));
    return r;
}

__device__ __forceinline__ void mma_tf32(float4& c, const uint32_t a[4], const uint32_t b[2]) {
    asm volatile(
        "mma.sync.aligned.m16n8k8.row.col.f32.tf32.tf32.f32 "
        "{%0,%1,%2,%3}, {%4,%5,%6,%7}, {%8,%9}, {%0,%1,%2,%3};"
        : "+f"(c.x), "+f"(c.y), "+f"(c.z), "+f"(c.w)
        : "r"(a[0]), "r"(a[1]), "r"(a[2]), "r"(a[3]), "r"(b[0]), "r"(b[1]));
}

// ---------------------------------------------------------------------------
// prep kernel: blocks [0,512): zero g_agg + scan h0 for nonzeros
//              blocks [512,512+126): tiny GEMMs rWr / qW (4 rows per block)
// ---------------------------------------------------------------------------
#define PREP_ZBLK 512
#define PREP_SBLK 126   // ceil(501/4)
__global__ void prep_kernel(const float* __restrict__ h0,
                            const float* __restrict__ re,
                            const float* __restrict__ Wr,
                            const float* __restrict__ Wqr,
                            const float* __restrict__ b_qr,
                            const int* __restrict__ q_rel) {
    if (blockIdx.x < PREP_ZBLK) {
        const size_t total = (size_t)N_NODE * DD / 4;
        float4 z = make_float4(0.f, 0.f, 0.f, 0.f);
        float4* p = (float4*)g_agg;
        const float4* hp = (const float4*)h0;
        size_t stride = (size_t)PREP_ZBLK * blockDim.x;
        bool nz = false;
        for (size_t i = (size_t)blockIdx.x * blockDim.x + threadIdx.x; i < total; i += stride) {
            p[i] = z;
            float4 v = hp[i];
            if (v.x != 0.f || v.y != 0.f || v.z != 0.f || v.w != 0.f) nz = true;
        }
        if (blockIdx.x == 0 && threadIdx.x == 0) g_h0nz = 0;
        if (nz) atomicOr(&g_h0nz, 1);
        return;
    }
    int b = (blockIdx.x - PREP_ZBLK) * 4 + (threadIdx.x >> 6);  // row 0..503
    int c = threadIdx.x & 63;
    if (b >= NRELROWS + NB) return;
    const float* row;
    const float* W;
    float* out;
    float acc;
    if (b < NRELROWS) {
        row = re + (size_t)b * DD;
        W = Wr;
        out = g_rWr + b * AA;
        acc = 0.f;
    } else {
        int bb = b - NRELROWS;
        row = re + (size_t)__ldg(&q_rel[bb]) * DD;
        W = Wqr;
        out = g_qW + bb * AA;
        acc = __ldg(&b_qr[c]);
    }
    for (int k = 0; k < DD; k++)
        acc += __ldg(&row[k]) * __ldg(&W[k * AA + c]);
    out[c] = acc;
}

// ---------------------------------------------------------------------------
// sws: g_sWs = hidden @ Ws  (TF32 mma).  M tile 64 (3 blocks/SM for latency
// hiding), 256 thr = 8 warps (2m x 4n).
// ---------------------------------------------------------------------------
#define SWS_SMEM ((64 * 132 + 128 * 72) * 4)  // 33792 + 36864 = 70656
__global__ __launch_bounds__(256) void sws_kernel(const float* __restrict__ A,
                                                  const float* __restrict__ B) {
    constexpr int LDA = 132, LDB = 72;
    extern __shared__ uint32_t sm[];
    uint32_t* sA = sm;             // [64][132]
    uint32_t* sB = sm + 64 * LDA;  // [128][72]
    int tid = threadIdx.x;
    int rowBase = blockIdx.x * 64;

    const float4* Av = (const float4*)A;
    for (int i = tid; i < 64 * 32; i += 256) {
        int r = i >> 5, kv = i & 31;
        int gr = rowBase + r;
        float4 v = (gr < N_NODE) ? Av[(size_t)gr * 32 + kv] : make_float4(0, 0, 0, 0);
        uint32_t* d = &sA[r * LDA + kv * 4];
        d[0] = f2tf32(v.x); d[1] = f2tf32(v.y); d[2] = f2tf32(v.z); d[3] = f2tf32(v.w);
    }
    const float4* Bv = (const float4*)B;
    for (int i = tid; i < 128 * 16; i += 256) {
        int r = i >> 4, c4 = i & 15;
        float4 v = Bv[i];
        uint32_t* d = &sB[r * LDB + c4 * 4];
        d[0] = f2tf32(v.x); d[1] = f2tf32(v.y); d[2] = f2tf32(v.z); d[3] = f2tf32(v.w);
    }
    __syncthreads();

    int lane = tid & 31, wid = tid >> 5;
    int gp = lane >> 2, tg = lane & 3;
    int warp_m = wid & 1, warp_n = wid >> 1;
    int m0 = warp_m * 32;
    int n0 = warp_n * 16;

    float4 acc[2][2];
#pragma unroll
    for (int mf = 0; mf < 2; mf++)
#pragma unroll
        for (int nf = 0; nf < 2; nf++) acc[mf][nf] = make_float4(0, 0, 0, 0);

    for (int kb = 0; kb < 128; kb += 8) {
        uint32_t a[2][4];
#pragma unroll
        for (int mf = 0; mf < 2; mf++) {
            const uint32_t* ap = &sA[(m0 + mf * 16 + gp) * LDA + kb + tg];
            a[mf][0] = ap[0];
            a[mf][2] = ap[4];
            const uint32_t* ap2 = ap + 8 * LDA;
            a[mf][1] = ap2[0];
            a[mf][3] = ap2[4];
        }
#pragma unroll
        for (int nf = 0; nf < 2; nf++) {
            const uint32_t* bp = &sB[(kb + tg) * LDB + n0 + nf * 8 + gp];
            uint32_t b[2] = {bp[0], bp[4 * LDB]};
            mma_tf32(acc[0][nf], a[0], b);
            mma_tf32(acc[1][nf], a[1], b);
        }
    }

#pragma unroll
    for (int mf = 0; mf < 2; mf++) {
        int r0 = rowBase + m0 + mf * 16 + gp;
#pragma unroll
        for (int nf = 0; nf < 2; nf++) {
            int c = n0 + nf * 8 + 2 * tg;
            float4 v = acc[mf][nf];
            if (r0 < N_NODE)
                *(float2*)&g_sWs[(size_t)r0 * AA + c] = make_float2(v.x, v.y);
            if (r0 + 8 < N_NODE)
                *(float2*)&g_sWs[(size_t)(r0 + 8) * AA + c] = make_float2(v.z, v.w);
        }
    }
}

// ---------------------------------------------------------------------------
// edge kernel: one warp per edge
// ---------------------------------------------------------------------------
__global__ void edge_kernel(const float* __restrict__ hidden,
                            const float* __restrict__ rela,
                            const float* __restrict__ w_alpha,
                            const float* __restrict__ b_alpha,
                            const int* __restrict__ r_idx,
                            const int* __restrict__ rel,
                            const int* __restrict__ sub,
                            const int* __restrict__ obj) {
    int e = (blockIdx.x * blockDim.x + threadIdx.x) >> 5;
    int lane = threadIdx.x & 31;
    if (e >= N_EDGE) return;

    int s  = __ldg(&sub[e]);
    int rl = __ldg(&rel[e]);
    int ri = __ldg(&r_idx[e]);
    int o  = __ldg(&obj[e]);

    const float2* sWs2 = (const float2*)g_sWs;
    const float2* rWr2 = (const float2*)g_rWr;
    const float2* qW2  = (const float2*)g_qW;

    float2 a0 = sWs2[(size_t)s * 32 + lane];
    float2 a1 = rWr2[rl * 32 + lane];
    float2 a2 = qW2[ri * 32 + lane];
    float ax = fmaxf(a0.x + a1.x + a2.x, 0.f);
    float ay = fmaxf(a0.y + a1.y + a2.y, 0.f);

    float2 wa = ((const float2*)w_alpha)[lane];
    float d = ax * wa.x + ay * wa.y;
#pragma unroll
    for (int off = 16; off; off >>= 1)
        d += __shfl_xor_sync(0xffffffffu, d, off);

    float alpha = sigmoidf_(d + __ldg(&b_alpha[0]));

    const float4* hv = (const float4*)hidden;
    const float4* rv = (const float4*)rela;
    float4 h4 = hv[(size_t)s * 32 + lane];
    float4 r4 = rv[(size_t)rl * 32 + lane];
    float4 m;
    m.x = alpha * (h4.x + r4.x);
    m.y = alpha * (h4.y + r4.y);
    m.z = alpha * (h4.z + r4.z);
    m.w = alpha * (h4.w + r4.w);

    float* dst = &g_agg[(size_t)o * DD + lane * 4];
    asm volatile("red.global.add.v4.f32 [%0], {%1,%2,%3,%4};"
                 :: "l"(dst), "f"(m.x), "f"(m.y), "f"(m.z), "f"(m.w)
                 : "memory");
}

// ---------------------------------------------------------------------------
// fused kernel: hn = relu(agg @ W_h) computed in-register per 128-row tile,
// restaged to smem as tf32, then gi = hn @ W_ih^T in two gate-aligned
// 64-column chunks (R/Z/N rows for the same output col live in one chunk),
// GRU gate math fused in the epilogue. g_hn never touches gmem.
// ---------------------------------------------------------------------------
#define FUSE_SMEM ((128 * 132 + 192 * 132) * 4)  // 67584 + 101376 = 168960
__global__ __launch_bounds__(256) void fused_kernel(const float* __restrict__ W_h,
                                                    const float* __restrict__ W_ih,
                                                    const float* __restrict__ W_hh,
                                                    const float* __restrict__ b_ih,
                                                    const float* __restrict__ b_hh,
                                                    const float* __restrict__ h0,
                                                    float* __restrict__ out) {
    constexpr int LDA = 132;   // agg tile / hn tile pad
    constexpr int LDB1 = 136;  // W_h (k-major) pad
    constexpr int LDB2 = 132;  // W_ih (n-major rows) pad
    extern __shared__ uint32_t sm[];
    uint32_t* sA = sm;              // [128][132]: agg tile, later hn tile
    uint32_t* sB = sm + 128 * LDA;  // region2: W_h [128][136] then W_ih chunk [192][132]
    int tid = threadIdx.x;
    int rowBase = blockIdx.x * 128;

    // ---- stage 0: load agg tile + W_h ----
    const float4* Av = (const float4*)g_agg;
    for (int i = tid; i < 128 * 32; i += 256) {
        int r = i >> 5, kv = i & 31;
        int gr = rowBase + r;
        float4 v = (gr < N_NODE) ? Av[(size_t)gr * 32 + kv] : make_float4(0, 0, 0, 0);
        uint32_t* d = &sA[r * LDA + kv * 4];
        d[0] = f2tf32(v.x); d[1] = f2tf32(v.y); d[2] = f2tf32(v.z); d[3] = f2tf32(v.w);
    }
    const float4* Whv = (const float4*)W_h;
    for (int i = tid; i < 128 * 32; i += 256) {
        int r = i >> 5, c4 = i & 31;
        float4 v = Whv[i];
        uint32_t* d = &sB[r * LDB1 + c4 * 4];
        d[0] = f2tf32(v.x); d[1] = f2tf32(v.y); d[2] = f2tf32(v.z); d[3] = f2tf32(v.w);
    }
    __syncthreads();

    int lane = tid & 31, wid = tid >> 5;
    int gp = lane >> 2, tg = lane & 3;
    int warp_m = wid & 3, warp_n = wid >> 2;
    int m0 = warp_m * 32;

    // ---- stage 1: hn tile = relu(agg @ W_h), acc in registers ----
    {
        int n0 = warp_n * 64;
        float4 acc[2][8];
#pragma unroll
        for (int mf = 0; mf < 2; mf++)
#pragma unroll
            for (int nf = 0; nf < 8; nf++) acc[mf][nf] = make_float4(0, 0, 0, 0);

        for (int kb = 0; kb < 128; kb += 8) {
            uint32_t a[2][4];
#pragma unroll
            for (int mf = 0; mf < 2; mf++) {
                const uint32_t* ap = &sA[(m0 + mf * 16 + gp) * LDA + kb + tg];
                a[mf][0] = ap[0];
                a[mf][2] = ap[4];
                const uint32_t* ap2 = ap + 8 * LDA;
                a[mf][1] = ap2[0];
                a[mf][3] = ap2[4];
            }
#pragma unroll
            for (int nf = 0; nf < 8; nf++) {
                const uint32_t* bp = &sB[(kb + tg) * LDB1 + n0 + nf * 8 + gp];
                uint32_t b[2] = {bp[0], bp[4 * LDB1]};
                mma_tf32(acc[0][nf], a[0], b);
                mma_tf32(acc[1][nf], a[1], b);
            }
        }
        __syncthreads();  // stage-1 reads done; safe to overwrite sA / sB

        // restage hn (relu, tf32) into sA
#pragma unroll
        for (int mf = 0; mf < 2; mf++) {
            int r0 = m0 + mf * 16 + gp;
#pragma unroll
            for (int nf = 0; nf < 8; nf++) {
                int c = n0 + nf * 8 + 2 * tg;
                float4 v = acc[mf][nf];
                sA[r0 * LDA + c]       = f2tf32(fmaxf(v.x, 0.f));
                sA[r0 * LDA + c + 1]   = f2tf32(fmaxf(v.y, 0.f));
                sA[(r0 + 8) * LDA + c]     = f2tf32(fmaxf(v.z, 0.f));
                sA[(r0 + 8) * LDA + c + 1] = f2tf32(fmaxf(v.w, 0.f));
            }
        }
    }

    // ---- stage 2: two gate-aligned chunks of 64 output cols each ----
    int flag = g_h0nz;
    const float4* Bv = (const float4*)W_ih;

    for (int chunk = 0; chunk < 2; chunk++) {
        // load W_ih rows {g*128 + chunk*64 + j : g in 0..2, j in 0..63}
        for (int i = tid; i < 192 * 32; i += 256) {
            int r = i >> 5, kv = i & 31;
            int g = r >> 6, j = r & 63;
            int grow = g * 128 + chunk * 64 + j;
            float4 v = Bv[(size_t)grow * 32 + kv];
            uint32_t* d = &sB[r * LDB2 + kv * 4];
            d[0] = f2tf32(v.x); d[1] = f2tf32(v.y); d[2] = f2tf32(v.z); d[3] = f2tf32(v.w);
        }
        __syncthreads();  // also covers hn writes on chunk 0

        float4 acc[2][12];
#pragma unroll
        for (int mf = 0; mf < 2; mf++)
#pragma unroll
            for (int nf = 0; nf < 12; nf++) acc[mf][nf] = make_float4(0, 0, 0, 0);

        for (int kb = 0; kb < 128; kb += 8) {
            uint32_t a[2][4];
#pragma unroll
            for (int mf = 0; mf < 2; mf++) {
                const uint32_t* ap = &sA[(m0 + mf * 16 + gp) * LDA + kb + tg];
                a[mf][0] = ap[0];
                a[mf][2] = ap[4];
                const uint32_t* ap2 = ap + 8 * LDA;
                a[mf][1] = ap2[0];
                a[mf][3] = ap2[4];
            }
#pragma unroll
            for (int nf = 0; nf < 12; nf++) {
                int g = nf >> 2, f = nf & 3;
                int brow = g * 64 + warp_n * 32 + f * 8 + gp;
                const uint32_t* bp = &sB[brow * LDB2 + kb + tg];
                uint32_t b[2] = {bp[0], bp[4]};
                mma_tf32(acc[0][nf], a[0], b);
                mma_tf32(acc[1][nf], a[1], b);
            }
        }

        // GRU epilogue for cols [chunk*64 + warp_n*32, +32)
#pragma unroll
        for (int mf = 0; mf < 2; mf++) {
            int r0 = rowBase + m0 + mf * 16 + gp;
#pragma unroll
            for (int f = 0; f < 4; f++) {
                float4 aR = acc[mf][f];
                float4 aZ = acc[mf][4 + f];
                float4 aN = acc[mf][8 + f];
                int cbase = chunk * 64 + warp_n * 32 + f * 8 + 2 * tg;
#pragma unroll
                for (int hi = 0; hi < 2; hi++) {
                    int row = r0 + hi * 8;
                    if (row >= N_NODE) continue;
                    float vr[2] = {hi ? aR.z : aR.x, hi ? aR.w : aR.y};
                    float vz[2] = {hi ? aZ.z : aZ.x, hi ? aZ.w : aZ.y};
                    float vn[2] = {hi ? aN.z : aN.x, hi ? aN.w : aN.y};
                    float o[2];
#pragma unroll
                    for (int p = 0; p < 2; p++) {
                        int c = cbase + p;
                        float gr_ = vr[p] + __ldg(&b_ih[c]) + __ldg(&b_hh[c]);
                        float gz_ = vz[p] + __ldg(&b_ih[128 + c]) + __ldg(&b_hh[128 + c]);
                        float gn_ = vn[p] + __ldg(&b_ih[256 + c]);
                        float ghn = __ldg(&b_hh[256 + c]);
                        float h0v = 0.f;
                        if (flag) {  // cold general path: gh = h0 @ W_hh^T
                            float sR = 0.f, sZ = 0.f, sN = 0.f;
                            for (int k = 0; k < DD; k++) {
                                float hv = __ldg(&h0[(size_t)row * DD + k]);
                                sR += hv * __ldg(&W_hh[(size_t)c * DD + k]);
                                sZ += hv * __ldg(&W_hh[(size_t)(128 + c) * DD + k]);
                                sN += hv * __ldg(&W_hh[(size_t)(256 + c) * DD + k]);
                            }
                            gr_ += sR;
                            gz_ += sZ;
                            ghn += sN;
                            h0v = __ldg(&h0[(size_t)row * DD + c]);
                        }
                        float rr = sigmoidf_(gr_);
                        float zz = sigmoidf_(gz_);
                        float nn = tanhf(gn_ + rr * ghn);
                        o[p] = (1.f - zz) * nn + zz * h0v;
                    }
                    *(float2*)&out[(size_t)row * DD + cbase] = make_float2(o[0], o[1]);
                }
            }
        }
        __syncthreads();  // protect sB before next chunk's load
    }
}

// ---------------------------------------------------------------------------
extern "C" void kernel_launch(void* const* d_in, const int* in_sizes, int n_in,
                              void* d_out, int out_size) {
    const float* hidden  = (const float*)d_in[0];
    const float* rela    = (const float*)d_in[1];
    const float* Ws      = (const float*)d_in[2];
    const float* Wr      = (const float*)d_in[3];
    const float* Wqr     = (const float*)d_in[4];
    const float* b_qr    = (const float*)d_in[5];
    const float* w_alpha = (const float*)d_in[6];
    const float* b_alpha = (const float*)d_in[7];
    const float* W_h     = (const float*)d_in[8];
    const float* W_ih    = (const float*)d_in[9];
    const float* W_hh    = (const float*)d_in[10];
    const float* b_ih    = (const float*)d_in[11];
    const float* b_hh    = (const float*)d_in[12];
    const float* h0      = (const float*)d_in[13];
    const int* q_rel     = (const int*)d_in[14];
    const int* r_idx     = (const int*)d_in[15];
    const int* rel       = (const int*)d_in[16];
    const int* sub       = (const int*)d_in[17];
    const int* obj       = (const int*)d_in[18];
    float* out = (float*)d_out;

    cudaFuncSetAttribute(sws_kernel, cudaFuncAttributeMaxDynamicSharedMemorySize, SWS_SMEM);
    cudaFuncSetAttribute(fused_kernel, cudaFuncAttributeMaxDynamicSharedMemorySize, FUSE_SMEM);

    prep_kernel<<<PREP_ZBLK + PREP_SBLK, 256>>>(h0, rela, Wr, Wqr, b_qr, q_rel);
    sws_kernel<<<(N_NODE + 63) / 64, 256, SWS_SMEM>>>(hidden, Ws);
    edge_kernel<<<(N_EDGE * 32 + 255) / 256, 256>>>(hidden, rela, w_alpha, b_alpha,
                                                    r_idx, rel, sub, obj);
    fused_kernel<<<(N_NODE + 127) / 128, 256, FUSE_SMEM>>>(W_h, W_ih, W_hh, b_ih,
                                                           b_hh, h0, out);
}

// round 6
// speedup vs baseline: 3.5537x; 1.2362x over previous
#include <cuda_runtime.h>
#include <math.h>
#include <stdint.h>

#define N_NODE 100000
#define N_EDGE 625000
#define DD 128
#define AA 64
#define NRELROWS 401
#define NB 100

// ---- scratch (device globals; no runtime allocation allowed) ----
__device__ float g_sWs[(size_t)N_NODE * AA];   // hidden @ Ws        [N,64]
__device__ float g_rWr[NRELROWS * AA];         // rela_embed @ Wr    [401,64]
__device__ float g_qW[NB * AA];                // rela[q_rel]@Wqr+b  [100,64]
__device__ float g_agg[(size_t)N_NODE * DD];   // segment_sum target [N,128]
__device__ int   g_h0nz;                       // 1 if h0 has any nonzero

__device__ __forceinline__ float sigmoidf_(float x) {
    return 1.0f / (1.0f + expf(-x));
}

__device__ __forceinline__ uint32_t f2tf32(float v) {
    uint32_t r;
    asm("cvt.rna.tf32.f32 %0, %1;" : "=r"(r) : "f"(v));
    return r;
}

__device__ __forceinline__ void mma_tf32(float4& c, const uint32_t a[4], const uint32_t b[2]) {
    asm volatile(
        "mma.sync.aligned.m16n8k8.row.col.f32.tf32.tf32.f32 "
        "{%0,%1,%2,%3}, {%4,%5,%6,%7}, {%8,%9}, {%0,%1,%2,%3};"
        : "+f"(c.x), "+f"(c.y), "+f"(c.z), "+f"(c.w)
        : "r"(a[0]), "r"(a[1]), "r"(a[2]), "r"(a[3]), "r"(b[0]), "r"(b[1]));
}

// ---------------------------------------------------------------------------
// prep kernel: blocks [0,512): zero g_agg + scan h0 for nonzeros
//              blocks [512,512+126): tiny GEMMs rWr / qW (4 rows per block)
// ---------------------------------------------------------------------------
#define PREP_ZBLK 512
#define PREP_SBLK 126   // ceil(501/4)
__global__ void prep_kernel(const float* __restrict__ h0,
                            const float* __restrict__ re,
                            const float* __restrict__ Wr,
                            const float* __restrict__ Wqr,
                            const float* __restrict__ b_qr,
                            const int* __restrict__ q_rel) {
    if (blockIdx.x < PREP_ZBLK) {
        const size_t total = (size_t)N_NODE * DD / 4;
        float4 z = make_float4(0.f, 0.f, 0.f, 0.f);
        float4* p = (float4*)g_agg;
        const float4* hp = (const float4*)h0;
        size_t stride = (size_t)PREP_ZBLK * blockDim.x;
        bool nz = false;
        for (size_t i = (size_t)blockIdx.x * blockDim.x + threadIdx.x; i < total; i += stride) {
            p[i] = z;
            float4 v = hp[i];
            if (v.x != 0.f || v.y != 0.f || v.z != 0.f || v.w != 0.f) nz = true;
        }
        if (blockIdx.x == 0 && threadIdx.x == 0) g_h0nz = 0;
        if (nz) atomicOr(&g_h0nz, 1);
        return;
    }
    int b = (blockIdx.x - PREP_ZBLK) * 4 + (threadIdx.x >> 6);  // row 0..503
    int c = threadIdx.x & 63;
    if (b >= NRELROWS + NB) return;
    const float* row;
    const float* W;
    float* out;
    float acc;
    if (b < NRELROWS) {
        row = re + (size_t)b * DD;
        W = Wr;
        out = g_rWr + b * AA;
        acc = 0.f;
    } else {
        int bb = b - NRELROWS;
        row = re + (size_t)__ldg(&q_rel[bb]) * DD;
        W = Wqr;
        out = g_qW + bb * AA;
        acc = __ldg(&b_qr[c]);
    }
    for (int k = 0; k < DD; k++)
        acc += __ldg(&row[k]) * __ldg(&W[k * AA + c]);
    out[c] = acc;
}

// ---------------------------------------------------------------------------
// sws: g_sWs = hidden @ Ws  (TF32 mma).  M tile 64, 3 blocks/SM.
// ---------------------------------------------------------------------------
#define SWS_SMEM ((64 * 132 + 128 * 72) * 4)  // 33792 + 36864 = 70656
__global__ __launch_bounds__(256) void sws_kernel(const float* __restrict__ A,
                                                  const float* __restrict__ B) {
    constexpr int LDA = 132, LDB = 72;
    extern __shared__ uint32_t sm[];
    uint32_t* sA = sm;             // [64][132]
    uint32_t* sB = sm + 64 * LDA;  // [128][72]
    int tid = threadIdx.x;
    int rowBase = blockIdx.x * 64;

    const float4* Av = (const float4*)A;
    for (int i = tid; i < 64 * 32; i += 256) {
        int r = i >> 5, kv = i & 31;
        int gr = rowBase + r;
        float4 v = (gr < N_NODE) ? Av[(size_t)gr * 32 + kv] : make_float4(0, 0, 0, 0);
        uint32_t* d = &sA[r * LDA + kv * 4];
        d[0] = f2tf32(v.x); d[1] = f2tf32(v.y); d[2] = f2tf32(v.z); d[3] = f2tf32(v.w);
    }
    const float4* Bv = (const float4*)B;
    for (int i = tid; i < 128 * 16; i += 256) {
        int r = i >> 4, c4 = i & 15;
        float4 v = Bv[i];
        uint32_t* d = &sB[r * LDB + c4 * 4];
        d[0] = f2tf32(v.x); d[1] = f2tf32(v.y); d[2] = f2tf32(v.z); d[3] = f2tf32(v.w);
    }
    __syncthreads();

    int lane = tid & 31, wid = tid >> 5;
    int gp = lane >> 2, tg = lane & 3;
    int warp_m = wid & 1, warp_n = wid >> 1;
    int m0 = warp_m * 32;
    int n0 = warp_n * 16;

    float4 acc[2][2];
#pragma unroll
    for (int mf = 0; mf < 2; mf++)
#pragma unroll
        for (int nf = 0; nf < 2; nf++) acc[mf][nf] = make_float4(0, 0, 0, 0);

    for (int kb = 0; kb < 128; kb += 8) {
        uint32_t a[2][4];
#pragma unroll
        for (int mf = 0; mf < 2; mf++) {
            const uint32_t* ap = &sA[(m0 + mf * 16 + gp) * LDA + kb + tg];
            a[mf][0] = ap[0];
            a[mf][2] = ap[4];
            const uint32_t* ap2 = ap + 8 * LDA;
            a[mf][1] = ap2[0];
            a[mf][3] = ap2[4];
        }
#pragma unroll
        for (int nf = 0; nf < 2; nf++) {
            const uint32_t* bp = &sB[(kb + tg) * LDB + n0 + nf * 8 + gp];
            uint32_t b[2] = {bp[0], bp[4 * LDB]};
            mma_tf32(acc[0][nf], a[0], b);
            mma_tf32(acc[1][nf], a[1], b);
        }
    }

#pragma unroll
    for (int mf = 0; mf < 2; mf++) {
        int r0 = rowBase + m0 + mf * 16 + gp;
#pragma unroll
        for (int nf = 0; nf < 2; nf++) {
            int c = n0 + nf * 8 + 2 * tg;
            float4 v = acc[mf][nf];
            if (r0 < N_NODE)
                *(float2*)&g_sWs[(size_t)r0 * AA + c] = make_float2(v.x, v.y);
            if (r0 + 8 < N_NODE)
                *(float2*)&g_sWs[(size_t)(r0 + 8) * AA + c] = make_float2(v.z, v.w);
        }
    }
}

// ---------------------------------------------------------------------------
// edge kernel: one warp per edge
// ---------------------------------------------------------------------------
__global__ void edge_kernel(const float* __restrict__ hidden,
                            const float* __restrict__ rela,
                            const float* __restrict__ w_alpha,
                            const float* __restrict__ b_alpha,
                            const int* __restrict__ r_idx,
                            const int* __restrict__ rel,
                            const int* __restrict__ sub,
                            const int* __restrict__ obj) {
    int e = (blockIdx.x * blockDim.x + threadIdx.x) >> 5;
    int lane = threadIdx.x & 31;
    if (e >= N_EDGE) return;

    int s  = __ldg(&sub[e]);
    int rl = __ldg(&rel[e]);
    int ri = __ldg(&r_idx[e]);
    int o  = __ldg(&obj[e]);

    const float2* sWs2 = (const float2*)g_sWs;
    const float2* rWr2 = (const float2*)g_rWr;
    const float2* qW2  = (const float2*)g_qW;

    float2 a0 = sWs2[(size_t)s * 32 + lane];
    float2 a1 = rWr2[rl * 32 + lane];
    float2 a2 = qW2[ri * 32 + lane];
    float ax = fmaxf(a0.x + a1.x + a2.x, 0.f);
    float ay = fmaxf(a0.y + a1.y + a2.y, 0.f);

    float2 wa = ((const float2*)w_alpha)[lane];
    float d = ax * wa.x + ay * wa.y;
#pragma unroll
    for (int off = 16; off; off >>= 1)
        d += __shfl_xor_sync(0xffffffffu, d, off);

    float alpha = sigmoidf_(d + __ldg(&b_alpha[0]));

    const float4* hv = (const float4*)hidden;
    const float4* rv = (const float4*)rela;
    float4 h4 = hv[(size_t)s * 32 + lane];
    float4 r4 = rv[(size_t)rl * 32 + lane];
    float4 m;
    m.x = alpha * (h4.x + r4.x);
    m.y = alpha * (h4.y + r4.y);
    m.z = alpha * (h4.z + r4.z);
    m.w = alpha * (h4.w + r4.w);

    float* dst = &g_agg[(size_t)o * DD + lane * 4];
    asm volatile("red.global.add.v4.f32 [%0], {%1,%2,%3,%4};"
                 :: "l"(dst), "f"(m.x), "f"(m.y), "f"(m.z), "f"(m.w)
                 : "memory");
}

// ---------------------------------------------------------------------------
// fused kernel (512 threads, 16 warps, 4m x 4n):
//   hn = relu(agg @ W_h) in-register per 128-row tile, restaged to smem tf32,
//   then gi = hn @ W_ih^T in two gate-aligned 64-col chunks, GRU epilogue.
// ---------------------------------------------------------------------------
#define FUSE_SMEM ((128 * 132 + 192 * 132) * 4)  // 67584 + 101376 = 168960
__global__ __launch_bounds__(512, 1) void fused_kernel(const float* __restrict__ W_h,
                                                       const float* __restrict__ W_ih,
                                                       const float* __restrict__ W_hh,
                                                       const float* __restrict__ b_ih,
                                                       const float* __restrict__ b_hh,
                                                       const float* __restrict__ h0,
                                                       float* __restrict__ out) {
    constexpr int LDA = 132;   // agg tile / hn tile pad
    constexpr int LDB1 = 136;  // W_h (k-major) pad
    constexpr int LDB2 = 132;  // W_ih (n-major rows) pad
    extern __shared__ uint32_t sm[];
    uint32_t* sA = sm;              // [128][132]: agg tile, later hn tile
    uint32_t* sB = sm + 128 * LDA;  // W_h [128][136] then W_ih chunk [192][132]
    int tid = threadIdx.x;
    int rowBase = blockIdx.x * 128;

    // ---- stage 0: load agg tile + W_h ----
    const float4* Av = (const float4*)g_agg;
    for (int i = tid; i < 128 * 32; i += 512) {
        int r = i >> 5, kv = i & 31;
        int gr = rowBase + r;
        float4 v = (gr < N_NODE) ? Av[(size_t)gr * 32 + kv] : make_float4(0, 0, 0, 0);
        uint32_t* d = &sA[r * LDA + kv * 4];
        d[0] = f2tf32(v.x); d[1] = f2tf32(v.y); d[2] = f2tf32(v.z); d[3] = f2tf32(v.w);
    }
    const float4* Whv = (const float4*)W_h;
    for (int i = tid; i < 128 * 32; i += 512) {
        int r = i >> 5, c4 = i & 31;
        float4 v = Whv[i];
        uint32_t* d = &sB[r * LDB1 + c4 * 4];
        d[0] = f2tf32(v.x); d[1] = f2tf32(v.y); d[2] = f2tf32(v.z); d[3] = f2tf32(v.w);
    }
    __syncthreads();

    int lane = tid & 31, wid = tid >> 5;
    int gp = lane >> 2, tg = lane & 3;
    int warp_m = wid & 3, warp_n = wid >> 2;  // 4 x 4
    int m0 = warp_m * 32;

    // ---- stage 1: hn tile = relu(agg @ W_h); each warp 32 rows x 32 cols ----
    {
        int n0 = warp_n * 32;
        float4 acc[2][4];
#pragma unroll
        for (int mf = 0; mf < 2; mf++)
#pragma unroll
            for (int nf = 0; nf < 4; nf++) acc[mf][nf] = make_float4(0, 0, 0, 0);

        for (int kb = 0; kb < 128; kb += 8) {
            uint32_t a[2][4];
#pragma unroll
            for (int mf = 0; mf < 2; mf++) {
                const uint32_t* ap = &sA[(m0 + mf * 16 + gp) * LDA + kb + tg];
                a[mf][0] = ap[0];
                a[mf][2] = ap[4];
                const uint32_t* ap2 = ap + 8 * LDA;
                a[mf][1] = ap2[0];
                a[mf][3] = ap2[4];
            }
#pragma unroll
            for (int nf = 0; nf < 4; nf++) {
                const uint32_t* bp = &sB[(kb + tg) * LDB1 + n0 + nf * 8 + gp];
                uint32_t b[2] = {bp[0], bp[4 * LDB1]};
                mma_tf32(acc[0][nf], a[0], b);
                mma_tf32(acc[1][nf], a[1], b);
            }
        }
        __syncthreads();  // stage-1 reads done; safe to overwrite sA / sB

        // restage hn (relu, tf32) into sA
#pragma unroll
        for (int mf = 0; mf < 2; mf++) {
            int r0 = m0 + mf * 16 + gp;
#pragma unroll
            for (int nf = 0; nf < 4; nf++) {
                int c = n0 + nf * 8 + 2 * tg;
                float4 v = acc[mf][nf];
                sA[r0 * LDA + c]       = f2tf32(fmaxf(v.x, 0.f));
                sA[r0 * LDA + c + 1]   = f2tf32(fmaxf(v.y, 0.f));
                sA[(r0 + 8) * LDA + c]     = f2tf32(fmaxf(v.z, 0.f));
                sA[(r0 + 8) * LDA + c + 1] = f2tf32(fmaxf(v.w, 0.f));
            }
        }
    }

    // ---- stage 2: two gate-aligned chunks of 64 output cols each ----
    int flag = g_h0nz;
    const float4* Bv = (const float4*)W_ih;

    for (int chunk = 0; chunk < 2; chunk++) {
        // load W_ih rows {g*128 + chunk*64 + j : g in 0..2, j in 0..63}
        for (int i = tid; i < 192 * 32; i += 512) {
            int r = i >> 5, kv = i & 31;
            int g = r >> 6, j = r & 63;
            int grow = g * 128 + chunk * 64 + j;
            float4 v = Bv[(size_t)grow * 32 + kv];
            uint32_t* d = &sB[r * LDB2 + kv * 4];
            d[0] = f2tf32(v.x); d[1] = f2tf32(v.y); d[2] = f2tf32(v.z); d[3] = f2tf32(v.w);
        }
        __syncthreads();  // also covers hn writes on chunk 0

        // each warp: 32 rows x 16 cols x 3 gates -> acc idx = gate*2 + f
        float4 acc[2][6];
#pragma unroll
        for (int mf = 0; mf < 2; mf++)
#pragma unroll
            for (int nf = 0; nf < 6; nf++) acc[mf][nf] = make_float4(0, 0, 0, 0);

        for (int kb = 0; kb < 128; kb += 8) {
            uint32_t a[2][4];
#pragma unroll
            for (int mf = 0; mf < 2; mf++) {
                const uint32_t* ap = &sA[(m0 + mf * 16 + gp) * LDA + kb + tg];
                a[mf][0] = ap[0];
                a[mf][2] = ap[4];
                const uint32_t* ap2 = ap + 8 * LDA;
                a[mf][1] = ap2[0];
                a[mf][3] = ap2[4];
            }
#pragma unroll
            for (int g = 0; g < 3; g++) {
#pragma unroll
                for (int f = 0; f < 2; f++) {
                    int brow = g * 64 + warp_n * 16 + f * 8 + gp;
                    const uint32_t* bp = &sB[brow * LDB2 + kb + tg];
                    uint32_t b[2] = {bp[0], bp[4]};
                    mma_tf32(acc[0][g * 2 + f], a[0], b);
                    mma_tf32(acc[1][g * 2 + f], a[1], b);
                }
            }
        }

        // GRU epilogue for cols [chunk*64 + warp_n*16, +16)
#pragma unroll
        for (int mf = 0; mf < 2; mf++) {
            int r0 = rowBase + m0 + mf * 16 + gp;
#pragma unroll
            for (int f = 0; f < 2; f++) {
                float4 aR = acc[mf][f];
                float4 aZ = acc[mf][2 + f];
                float4 aN = acc[mf][4 + f];
                int cbase = chunk * 64 + warp_n * 16 + f * 8 + 2 * tg;
#pragma unroll
                for (int hi = 0; hi < 2; hi++) {
                    int row = r0 + hi * 8;
                    if (row >= N_NODE) continue;
                    float vr[2] = {hi ? aR.z : aR.x, hi ? aR.w : aR.y};
                    float vz[2] = {hi ? aZ.z : aZ.x, hi ? aZ.w : aZ.y};
                    float vn[2] = {hi ? aN.z : aN.x, hi ? aN.w : aN.y};
                    float o[2];
#pragma unroll
                    for (int p = 0; p < 2; p++) {
                        int c = cbase + p;
                        float gr_ = vr[p] + __ldg(&b_ih[c]) + __ldg(&b_hh[c]);
                        float gz_ = vz[p] + __ldg(&b_ih[128 + c]) + __ldg(&b_hh[128 + c]);
                        float gn_ = vn[p] + __ldg(&b_ih[256 + c]);
                        float ghn = __ldg(&b_hh[256 + c]);
                        float h0v = 0.f;
                        if (flag) {  // cold general path: gh = h0 @ W_hh^T
                            float sR = 0.f, sZ = 0.f, sN = 0.f;
                            for (int k = 0; k < DD; k++) {
                                float hv = __ldg(&h0[(size_t)row * DD + k]);
                                sR += hv * __ldg(&W_hh[(size_t)c * DD + k]);
                                sZ += hv * __ldg(&W_hh[(size_t)(128 + c) * DD + k]);
                                sN += hv * __ldg(&W_hh[(size_t)(256 + c) * DD + k]);
                            }
                            gr_ += sR;
                            gz_ += sZ;
                            ghn += sN;
                            h0v = __ldg(&h0[(size_t)row * DD + c]);
                        }
                        float rr = sigmoidf_(gr_);
                        float zz = sigmoidf_(gz_);
                        float nn = tanhf(gn_ + rr * ghn);
                        o[p] = (1.f - zz) * nn + zz * h0v;
                    }
                    *(float2*)&out[(size_t)row * DD + cbase] = make_float2(o[0], o[1]);
                }
            }
        }
        __syncthreads();  // protect sB before next chunk's load
    }
}

// ---------------------------------------------------------------------------
extern "C" void kernel_launch(void* const* d_in, const int* in_sizes, int n_in,
                              void* d_out, int out_size) {
    const float* hidden  = (const float*)d_in[0];
    const float* rela    = (const float*)d_in[1];
    const float* Ws      = (const float*)d_in[2];
    const float* Wr      = (const float*)d_in[3];
    const float* Wqr     = (const float*)d_in[4];
    const float* b_qr    = (const float*)d_in[5];
    const float* w_alpha = (const float*)d_in[6];
    const float* b_alpha = (const float*)d_in[7];
    const float* W_h     = (const float*)d_in[8];
    const float* W_ih    = (const float*)d_in[9];
    const float* W_hh    = (const float*)d_in[10];
    const float* b_ih    = (const float*)d_in[11];
    const float* b_hh    = (const float*)d_in[12];
    const float* h0      = (const float*)d_in[13];
    const int* q_rel     = (const int*)d_in[14];
    const int* r_idx     = (const int*)d_in[15];
    const int* rel       = (const int*)d_in[16];
    const int* sub       = (const int*)d_in[17];
    const int* obj       = (const int*)d_in[18];
    float* out = (float*)d_out;

    cudaFuncSetAttribute(sws_kernel, cudaFuncAttributeMaxDynamicSharedMemorySize, SWS_SMEM);
    cudaFuncSetAttribute(fused_kernel, cudaFuncAttributeMaxDynamicSharedMemorySize, FUSE_SMEM);

    prep_kernel<<<PREP_ZBLK + PREP_SBLK, 256>>>(h0, rela, Wr, Wqr, b_qr, q_rel);
    sws_kernel<<<(N_NODE + 63) / 64, 256, SWS_SMEM>>>(hidden, Ws);
    edge_kernel<<<(N_EDGE * 32 + 255) / 256, 256>>>(hidden, rela, w_alpha, b_alpha,
                                                    r_idx, rel, sub, obj);
    fused_kernel<<<(N_NODE + 127) / 128, 512, FUSE_SMEM>>>(W_h, W_ih, W_hh, b_ih,
                                                           b_hh, h0, out);
}